// round 16
// baseline (speedup 1.0000x reference)
#include <cuda_runtime.h>
#include <cuda_fp16.h>
#include <stdint.h>

// ---------------- constants ----------------
#define TM 128
#define TN 128
#define KC 64                       // k-slab (fp16 elements)
#define RS 72                       // smem row stride in fp16 elems (144 B, conflict-free)
#define TILE_B (128 * RS * 2)       // 18432 B per tile
#define STAGE_B (2 * TILE_B)        // A + B tiles = 36864
#define NS 3
#define SMEM_DYN (NS * STAGE_B)     // 110592
#define NTHREADS 128

// ctl layout: [0]=ticket, [1..256]=cnt_qk(z*128+rowtile), [257..288]=cnt_vt(bz*8+ntile),
//             [289..416]=cnt_sc(bz*32+rowtile)
#define CTL_QK 1
#define CTL_VT 257
#define CTL_SC 289

// ---------------- static scratch ----------------
__device__ __half g_Xh [16384L*1024];
__device__ __half g_Wh [3L*1024*1024];     // WqT, WkT, WvT (each [n,e])
__device__ __half g_Qs [16384L*1024];
__device__ __half g_Ks [16384L*1024];
__device__ __half g_Vt [16384L*1024];      // [b][n, s]
__device__ __half g_Ph [67108864L];        // unnormalized exp(scores)
__device__ float  g_rs [16384];            // per-row softmax denominators
__device__ int    g_ctl[512];              // ticket + dataflow counters

// ---------------- helpers ----------------
__device__ __forceinline__ uint32_t smem_u32(const void* p) {
    uint32_t r;
    asm("{ .reg .u64 t; cvta.to.shared.u64 t, %1; cvt.u32.u64 %0, t; }" : "=r"(r) : "l"(p));
    return r;
}

__device__ __forceinline__ uint32_t packh(__half a, __half b) {
    return ((uint32_t)__half_as_ushort(b) << 16) | (uint32_t)__half_as_ushort(a);
}

__device__ __forceinline__ void ldsm4(uint32_t* r, uint32_t addr) {
    asm volatile("ldmatrix.sync.aligned.m8n8.x4.shared.b16 {%0,%1,%2,%3}, [%4];"
                 : "=r"(r[0]), "=r"(r[1]), "=r"(r[2]), "=r"(r[3]) : "r"(addr));
}

// non-volatile: pure register op, lets ptxas schedule around it
__device__ __forceinline__ void mma16816(float* c, const uint32_t* a, const uint32_t* b) {
    asm("mma.sync.aligned.m16n8k16.row.col.f32.f16.f16.f32 "
        "{%0,%1,%2,%3}, {%4,%5,%6,%7}, {%8,%9}, {%0,%1,%2,%3};"
        : "+f"(c[0]), "+f"(c[1]), "+f"(c[2]), "+f"(c[3])
        : "r"(a[0]), "r"(a[1]), "r"(a[2]), "r"(a[3]), "r"(b[0]), "r"(b[1]));
}

// .cg = L2-only (bypass L1)
__device__ __forceinline__ void cpa16(uint32_t dst, const void* src) {
    asm volatile("cp.async.cg.shared.global [%0], [%1], 16;" :: "r"(dst), "l"(src));
}

template <int N>
__device__ __forceinline__ void cpwait() {
    asm volatile("cp.async.wait_group %0;" :: "n"(N) : "memory");
}

// consumer: tid0 spins on an L2-routed load until *p >= target
__device__ __forceinline__ void wait_cnt(const int* p, int target) {
    if (threadIdx.x == 0) {
        int v;
        do {
            asm volatile("ld.global.cg.b32 %0, [%1];" : "=r"(v) : "l"(p));
            if (v < target) __nanosleep(128);
        } while (v < target);
    }
    __syncthreads();
    __threadfence();
}

// producer: all threads fence their writes, then one arrival
__device__ __forceinline__ void arrive_cnt(int* p) {
    __threadfence();
    __syncthreads();
    if (threadIdx.x == 0) atomicAdd(p, 1);
}

// stage one 128x64-fp16 tile (k-contiguous rows, 128 B payload per row), 128 threads
__device__ __forceinline__ void stage_tile(uint32_t dstb, const char* src, long ldbytes, int tid) {
#pragma unroll
    for (int t = 0; t < 8; t++) {
        int j = tid + t * NTHREADS;
        int r = j >> 3;
        int c = j & 7;
        cpa16(dstb + r * (RS * 2) + c * 16, src + (long)r * ldbytes + c * 16);
    }
}

// Shared mainloop: K-slab cp.async pipeline, 64x64 warp tiles, acc[4][8][4].
struct MainloopArgs {
    uint32_t sb;
    const char *pA, *pB;
    long ldab, ldbb;
    int aOffBase, bOffBase;
    int nslab, tid;
};

__device__ __forceinline__ void run_mainloop(const MainloopArgs& g, float acc[4][8][4]) {
    auto stage = [&](int idx) {
        const uint32_t base = g.sb + (uint32_t)(idx % NS) * STAGE_B;
        const long kb = (long)idx * (KC * 2);
        stage_tile(base + 0, g.pA + kb, g.ldab, g.tid);
        stage_tile(base + TILE_B, g.pB + kb, g.ldbb, g.tid);
        asm volatile("cp.async.commit_group;" ::: "memory");
    };

#pragma unroll
    for (int p = 0; p < NS - 1; p++) stage(p);

    for (int s = 0; s < g.nslab; s++) {
        if (s + 1 < g.nslab) cpwait<1>(); else cpwait<0>();
        __syncthreads();   // single barrier per slab

        const uint32_t st = g.sb + (uint32_t)(s % NS) * STAGE_B;

        uint32_t ah[2][4][4];
#pragma unroll
        for (int i = 0; i < 4; i++)
            ldsm4(ah[0][i], st + g.aOffBase + i * 16 * (RS * 2));

#pragma unroll
        for (int kk = 0; kk < 4; kk++) {
            const int cur = kk & 1;
            const int ko = kk * 32;
            uint32_t bh[8][2];
#pragma unroll
            for (int jp = 0; jp < 4; jp++) {
                uint32_t r[4];
                ldsm4(r, st + TILE_B + g.bOffBase + jp * 16 * (RS * 2) + ko);
                bh[2 * jp][0] = r[0]; bh[2 * jp][1] = r[1];
                bh[2 * jp + 1][0] = r[2]; bh[2 * jp + 1][1] = r[3];
            }
            if (kk < 3) {
#pragma unroll
                for (int i = 0; i < 4; i++)
                    ldsm4(ah[cur ^ 1][i], st + g.aOffBase + i * 16 * (RS * 2) + ko + 32);
            }
#pragma unroll
            for (int i = 0; i < 4; i++)
#pragma unroll
                for (int j = 0; j < 8; j++) mma16816(acc[i][j], ah[cur][i], bh[j]);
        }

        if (s + NS - 1 < g.nslab) stage(s + NS - 1);
    }
}

// ---------------- mega kernel: all four GEMM phases, ticket-ordered ----------------
// tickets: [0,2048) QK-proj  [2048,3072) Vt-proj  [3072,7168) scores  [7168,8192) PV
__global__ void __launch_bounds__(NTHREADS, 2)
mega(const __half* __restrict__ Xh, const __half* __restrict__ Wh,
     const float* __restrict__ bq, const float* __restrict__ bk,
     const float* __restrict__ bv,
     __half* __restrict__ Qs, __half* __restrict__ Ks,
     __half* __restrict__ Vt, __half* __restrict__ Ph,
     float* __restrict__ rs, int* __restrict__ ctl,
     float* __restrict__ out)
{
    extern __shared__ __align__(16) char smraw[];
    const uint32_t sb = smem_u32(smraw);

    const int tid = threadIdx.x;
    const int wid = tid >> 5;
    const int lane = tid & 31;
    const int wm = (wid & 1) * 64;
    const int wn = (wid >> 1) * 64;
    const int aOffBase = (wm + (lane & 15)) * (RS * 2) + ((lane >> 4) << 4);
    const int bOffBase = (wn + ((lane >> 4) << 3) + (lane & 7)) * (RS * 2) + (((lane >> 3) & 1) << 4);

    __shared__ int s_t;
    if (tid == 0) s_t = atomicAdd(&ctl[0], 1);
    __syncthreads();
    const int t = s_t;

    float acc[4][8][4];
#pragma unroll
    for (int i = 0; i < 4; i++)
#pragma unroll
        for (int j = 0; j < 8; j++)
#pragma unroll
            for (int e = 0; e < 4; e++) acc[i][j][e] = 0.f;

    MainloopArgs g;
    g.sb = sb;
    g.aOffBase = aOffBase;
    g.bOffBase = bOffBase;
    g.tid = tid;

    if (t < 2048) {
        // ---- QK projection: C[s, n] = X * W^T + b, fp16 out ----
        const int z = t >> 10;           // 0=Q, 1=K
        const int tt = t & 1023;
        const long m0 = (long)(tt >> 3) * TM;   // row tile 0..127 (16384 rows)
        const long n0 = (long)(tt & 7) * TN;    // col tile 0..7
        const float* bp = z ? bk : bq;
        __half* C = (z ? Ks : Qs);

        g.pA = (const char*)(Xh + m0 * 1024);
        g.pB = (const char*)(Wh + (long)z * 1048576L + n0 * 1024);
        g.ldab = 2048; g.ldbb = 2048; g.nslab = 16;
        run_mainloop(g, acc);

#pragma unroll
        for (int i = 0; i < 4; i++) {
            const long r0 = m0 + wm + i * 16 + (lane >> 2);
            const long r1 = r0 + 8;
#pragma unroll
            for (int j = 0; j < 8; j++) {
                const int cb = (int)n0 + wn + j * 8 + (lane & 3) * 2;
                const float b0 = bp[cb], b1 = bp[cb + 1];
                *(uint32_t*)(C + r0 * 1024 + cb) =
                    packh(__float2half_rn(acc[i][j][0] + b0),
                          __float2half_rn(acc[i][j][1] + b1));
                *(uint32_t*)(C + r1 * 1024 + cb) =
                    packh(__float2half_rn(acc[i][j][2] + b0),
                          __float2half_rn(acc[i][j][3] + b1));
            }
        }
        arrive_cnt(&ctl[CTL_QK + z * 128 + (tt >> 3)]);

    } else if (t < 3072) {
        // ---- Vt projection: Vt[n, s] = WvT x X^T + bv(row), per batch ----
        const int t2 = t - 2048;
        const long bz = t2 >> 8;
        const int tt = t2 & 255;
        const int ntile = tt >> 5;               // 0..7 (n dim, 1024)
        const long m0 = (long)ntile * TM;
        const long n0 = (long)(tt & 31) * TN;    // s dim, 4096

        g.pA = (const char*)(Wh + 2097152L + m0 * 1024);
        g.pB = (const char*)(Xh + bz * 4194304L + n0 * 1024);
        g.ldab = 2048; g.ldbb = 2048; g.nslab = 16;
        run_mainloop(g, acc);

        __half* outb = Vt + bz * 4194304L;
#pragma unroll
        for (int i = 0; i < 4; i++) {
            const long r0 = m0 + wm + i * 16 + (lane >> 2);
            const long r1 = r0 + 8;
            const float rb0 = bv[r0], rb1 = bv[r1];
#pragma unroll
            for (int j = 0; j < 8; j++) {
                const int cb = (int)n0 + wn + j * 8 + (lane & 3) * 2;
                *(uint32_t*)(outb + r0 * 4096 + cb) =
                    packh(__float2half_rn(acc[i][j][0] + rb0),
                          __float2half_rn(acc[i][j][1] + rb0));
                *(uint32_t*)(outb + r1 * 4096 + cb) =
                    packh(__float2half_rn(acc[i][j][2] + rb1),
                          __float2half_rn(acc[i][j][3] + rb1));
            }
        }
        arrive_cnt(&ctl[CTL_VT + (int)bz * 8 + ntile]);

    } else if (t < 7168) {
        // ---- scores: Ph = exp((1/32) Q K^T) + rowsum atomics ----
        const int t2 = t - 3072;
        const long bz = t2 >> 10;
        const int tt = t2 & 1023;
        const int yt = tt >> 5, xt = tt & 31;
        const long m0 = (long)yt * TM;
        const long n0 = (long)xt * TN;

        wait_cnt(&ctl[CTL_QK + 0 + (int)bz * 32 + yt], 8);
        wait_cnt(&ctl[CTL_QK + 128 + (int)bz * 32 + xt], 8);

        g.pA = (const char*)(Qs + bz * 4194304L + m0 * 1024);
        g.pB = (const char*)(Ks + bz * 4194304L + n0 * 1024);
        g.ldab = 2048; g.ldbb = 2048; g.nslab = 16;
        run_mainloop(g, acc);

        __half* outb = Ph + bz * 16777216L;
#pragma unroll
        for (int i = 0; i < 4; i++) {
            const long r0 = m0 + wm + i * 16 + (lane >> 2);
            const long r1 = r0 + 8;
            float s0 = 0.f, s1 = 0.f;
#pragma unroll
            for (int j = 0; j < 8; j++) {
                const int cb = (int)n0 + wn + j * 8 + (lane & 3) * 2;
                const float e0 = __expf(0.03125f * acc[i][j][0]);
                const float e1 = __expf(0.03125f * acc[i][j][1]);
                const float e2 = __expf(0.03125f * acc[i][j][2]);
                const float e3 = __expf(0.03125f * acc[i][j][3]);
                s0 += e0 + e1;
                s1 += e2 + e3;
                *(uint32_t*)(outb + r0 * 4096 + cb) =
                    packh(__float2half_rn(e0), __float2half_rn(e1));
                *(uint32_t*)(outb + r1 * 4096 + cb) =
                    packh(__float2half_rn(e2), __float2half_rn(e3));
            }
            s0 += __shfl_xor_sync(0xffffffffu, s0, 1);
            s0 += __shfl_xor_sync(0xffffffffu, s0, 2);
            s1 += __shfl_xor_sync(0xffffffffu, s1, 1);
            s1 += __shfl_xor_sync(0xffffffffu, s1, 2);
            if ((lane & 3) == 0) {
                atomicAdd(&rs[bz * 4096 + r0], s0);
                atomicAdd(&rs[bz * 4096 + r1], s1);
            }
        }
        arrive_cnt(&ctl[CTL_SC + (int)bz * 32 + yt]);

    } else {
        // ---- PV: out = (P~ V) / rowsum, fp32 ----
        const int t2 = t - 7168;
        const long bz = t2 >> 8;
        const int tt = t2 & 255;
        const int xt = tt & 7;                    // n tile of 1024
        const int yt = tt >> 3;                   // m tile of 4096
        const long m0 = (long)yt * TM;
        const long n0 = (long)xt * TN;

        wait_cnt(&ctl[CTL_SC + (int)bz * 32 + yt], 32);   // Ph rows + rowsum final
        wait_cnt(&ctl[CTL_VT + (int)bz * 8 + xt], 32);    // Vt rows ready

        g.pA = (const char*)(Ph + bz * 16777216L + m0 * 4096);
        g.pB = (const char*)(Vt + bz * 4194304L + n0 * 4096);
        g.ldab = 8192; g.ldbb = 8192; g.nslab = 64;
        run_mainloop(g, acc);

        float* outb = out + bz * 4194304L;
#pragma unroll
        for (int i = 0; i < 4; i++) {
            const long r0 = m0 + wm + i * 16 + (lane >> 2);
            const long r1 = r0 + 8;
            const float inv0 = __frcp_rn(__ldg(&rs[bz * 4096 + r0]));
            const float inv1 = __frcp_rn(__ldg(&rs[bz * 4096 + r1]));
#pragma unroll
            for (int j = 0; j < 8; j++) {
                const int cb = (int)n0 + wn + j * 8 + (lane & 3) * 2;
                *(float2*)(outb + r0 * 1024 + cb) =
                    make_float2(acc[i][j][0] * inv0, acc[i][j][1] * inv0);
                *(float2*)(outb + r1 * 1024 + cb) =
                    make_float2(acc[i][j][2] * inv1, acc[i][j][3] * inv1);
            }
        }
    }
}

// ---------------- pre passes ----------------
__global__ void __launch_bounds__(256) convert_x(const float4* __restrict__ x,
                                                 uint2* __restrict__ h)
{
    long i = (long)blockIdx.x * 256 + threadIdx.x;
    float4 v = x[i];
    h[i] = make_uint2(packh(__float2half_rn(v.x), __float2half_rn(v.y)),
                      packh(__float2half_rn(v.z), __float2half_rn(v.w)));
}

// W[e,n] -> Wt[n,e] fp16
__global__ void __launch_bounds__(256) convert_wt(const float* __restrict__ W0,
                                                  const float* __restrict__ W1,
                                                  const float* __restrict__ W2,
                                                  __half* __restrict__ hi)
{
    const float* W = (blockIdx.z == 0) ? W0 : (blockIdx.z == 1) ? W1 : W2;
    __half* ho = hi + (long)blockIdx.z * 1048576;
    __shared__ float t[32][33];
    const int e0 = blockIdx.x * 32, n0 = blockIdx.y * 32;
    const int lx = threadIdx.x & 31, ly = threadIdx.x >> 5;
#pragma unroll
    for (int j = 0; j < 4; j++)
        t[ly + 8 * j][lx] = W[(long)(e0 + ly + 8 * j) * 1024 + n0 + lx];
    __syncthreads();
#pragma unroll
    for (int j = 0; j < 4; j++)
        ho[(long)(n0 + ly + 8 * j) * 1024 + e0 + lx] = __float2half_rn(t[lx][ly + 8 * j]);
}

// ---------------- launch ----------------
extern "C" void kernel_launch(void* const* d_in, const int* in_sizes, int n_in,
                              void* d_out, int out_size)
{
    const float* x  = (const float*)d_in[0];
    const float* Wq = (const float*)d_in[1];
    const float* bq = (const float*)d_in[2];
    const float* Wk = (const float*)d_in[3];
    const float* bk = (const float*)d_in[4];
    const float* Wv = (const float*)d_in[5];
    const float* bv = (const float*)d_in[6];
    float* out = (float*)d_out;

    __half *Xh, *Wh, *Qs, *Ks, *Vt, *Ph;
    float* rs;
    int* ctl;
    cudaGetSymbolAddress((void**)&Xh, g_Xh);
    cudaGetSymbolAddress((void**)&Wh, g_Wh);
    cudaGetSymbolAddress((void**)&Qs, g_Qs);
    cudaGetSymbolAddress((void**)&Ks, g_Ks);
    cudaGetSymbolAddress((void**)&Vt, g_Vt);
    cudaGetSymbolAddress((void**)&Ph, g_Ph);
    cudaGetSymbolAddress((void**)&rs, g_rs);
    cudaGetSymbolAddress((void**)&ctl, g_ctl);

    cudaFuncSetAttribute(mega, cudaFuncAttributeMaxDynamicSharedMemorySize, SMEM_DYN);

    // 0. reset ticket/counters + softmax denominators
    cudaMemsetAsync(ctl, 0, 512 * sizeof(int));
    cudaMemsetAsync(rs, 0, 16384 * sizeof(float));

    // 1. operand conversion
    convert_x<<<16384, 256>>>((const float4*)x, (uint2*)Xh);
    convert_wt<<<dim3(32, 32, 3), 256>>>(Wq, Wk, Wv, Wh);

    // 2. everything else: one ticket-ordered mega launch
    mega<<<8192, NTHREADS, SMEM_DYN>>>(
        Xh, Wh, bq, bk, bv, Qs, Ks, Vt, Ph, rs, ctl, out);
}

// round 17
// speedup vs baseline: 1.0096x; 1.0096x over previous
#include <cuda_runtime.h>
#include <cuda_fp16.h>
#include <stdint.h>

// ---------------- constants ----------------
#define TM 128
#define TN 128
#define KC 64                       // k-slab (fp16 elements)
#define RS 72                       // smem row stride in fp16 elems (144 B, conflict-free)
#define TILE_B (128 * RS * 2)       // 18432 B per tile
#define STAGE_B (2 * TILE_B)        // A + B tiles = 36864
#define NS 3
#define SMEM_DYN (NS * STAGE_B)     // 110592
#define NTHREADS 128

// ctl: [0]=ticket, [32..64)=cnt_vt (bz*8+ntile), [64..192)=cnt_sc (bz*32+yt)
#define CTL_VT 32
#define CTL_SC 64

// ---------------- static scratch ----------------
__device__ __half g_Xh [16384L*1024];
__device__ __half g_Wh [3L*1024*1024];     // WqT, WkT, WvT (each [n,e])
__device__ __half g_Qs [16384L*1024];
__device__ __half g_Ks [16384L*1024];
__device__ __half g_Vt [16384L*1024];      // [b][n, s]
__device__ __half g_Ph [67108864L];        // unnormalized exp(scores)
__device__ float  g_rs [16384];            // per-row softmax denominators
__device__ int    g_ctl[512];              // ticket + dataflow counters

// ---------------- helpers ----------------
__device__ __forceinline__ uint32_t smem_u32(const void* p) {
    uint32_t r;
    asm("{ .reg .u64 t; cvta.to.shared.u64 t, %1; cvt.u32.u64 %0, t; }" : "=r"(r) : "l"(p));
    return r;
}

__device__ __forceinline__ uint32_t packh(__half a, __half b) {
    return ((uint32_t)__half_as_ushort(b) << 16) | (uint32_t)__half_as_ushort(a);
}

__device__ __forceinline__ void ldsm4(uint32_t* r, uint32_t addr) {
    asm volatile("ldmatrix.sync.aligned.m8n8.x4.shared.b16 {%0,%1,%2,%3}, [%4];"
                 : "=r"(r[0]), "=r"(r[1]), "=r"(r[2]), "=r"(r[3]) : "r"(addr));
}

// non-volatile: pure register op, lets ptxas schedule around it
__device__ __forceinline__ void mma16816(float* c, const uint32_t* a, const uint32_t* b) {
    asm("mma.sync.aligned.m16n8k16.row.col.f32.f16.f16.f32 "
        "{%0,%1,%2,%3}, {%4,%5,%6,%7}, {%8,%9}, {%0,%1,%2,%3};"
        : "+f"(c[0]), "+f"(c[1]), "+f"(c[2]), "+f"(c[3])
        : "r"(a[0]), "r"(a[1]), "r"(a[2]), "r"(a[3]), "r"(b[0]), "r"(b[1]));
}

// .cg = L2-only (bypass L1)
__device__ __forceinline__ void cpa16(uint32_t dst, const void* src) {
    asm volatile("cp.async.cg.shared.global [%0], [%1], 16;" :: "r"(dst), "l"(src));
}

template <int N>
__device__ __forceinline__ void cpwait() {
    asm volatile("cp.async.wait_group %0;" :: "n"(N) : "memory");
}

// consumer: tid0 spins on an L2-routed load until *p >= target
__device__ __forceinline__ void wait_cnt(const int* p, int target) {
    if (threadIdx.x == 0) {
        int v;
        do {
            asm volatile("ld.global.cg.b32 %0, [%1];" : "=r"(v) : "l"(p));
            if (v < target) __nanosleep(128);
        } while (v < target);
    }
    __syncthreads();
    __threadfence();
}

// producer: all threads fence their writes, then one arrival
__device__ __forceinline__ void arrive_cnt(int* p) {
    __threadfence();
    __syncthreads();
    if (threadIdx.x == 0) atomicAdd(p, 1);
}

// stage one 128x64-fp16 tile (k-contiguous rows, 128 B payload per row), 128 threads
__device__ __forceinline__ void stage_tile(uint32_t dstb, const char* src, long ldbytes, int tid) {
#pragma unroll
    for (int t = 0; t < 8; t++) {
        int j = tid + t * NTHREADS;
        int r = j >> 3;
        int c = j & 7;
        cpa16(dstb + r * (RS * 2) + c * 16, src + (long)r * ldbytes + c * 16);
    }
}

// Shared mainloop: K-slab cp.async pipeline, 64x64 warp tiles, acc[4][8][4].
struct MainloopArgs {
    uint32_t sb;
    const char *pA, *pB;
    long ldab, ldbb;
    int aOffBase, bOffBase;
    int nslab, tid;
};

__device__ __forceinline__ void run_mainloop(const MainloopArgs& g, float acc[4][8][4]) {
    auto stage = [&](int idx) {
        const uint32_t base = g.sb + (uint32_t)(idx % NS) * STAGE_B;
        const long kb = (long)idx * (KC * 2);
        stage_tile(base + 0, g.pA + kb, g.ldab, g.tid);
        stage_tile(base + TILE_B, g.pB + kb, g.ldbb, g.tid);
        asm volatile("cp.async.commit_group;" ::: "memory");
    };

#pragma unroll
    for (int p = 0; p < NS - 1; p++) stage(p);

    for (int s = 0; s < g.nslab; s++) {
        if (s + 1 < g.nslab) cpwait<1>(); else cpwait<0>();
        __syncthreads();   // single barrier per slab

        const uint32_t st = g.sb + (uint32_t)(s % NS) * STAGE_B;

        uint32_t ah[2][4][4];
#pragma unroll
        for (int i = 0; i < 4; i++)
            ldsm4(ah[0][i], st + g.aOffBase + i * 16 * (RS * 2));

#pragma unroll
        for (int kk = 0; kk < 4; kk++) {
            const int cur = kk & 1;
            const int ko = kk * 32;
            uint32_t bh[8][2];
#pragma unroll
            for (int jp = 0; jp < 4; jp++) {
                uint32_t r[4];
                ldsm4(r, st + TILE_B + g.bOffBase + jp * 16 * (RS * 2) + ko);
                bh[2 * jp][0] = r[0]; bh[2 * jp][1] = r[1];
                bh[2 * jp + 1][0] = r[2]; bh[2 * jp + 1][1] = r[3];
            }
            if (kk < 3) {
#pragma unroll
                for (int i = 0; i < 4; i++)
                    ldsm4(ah[cur ^ 1][i], st + g.aOffBase + i * 16 * (RS * 2) + ko + 32);
            }
#pragma unroll
            for (int i = 0; i < 4; i++)
#pragma unroll
                for (int j = 0; j < 8; j++) mma16816(acc[i][j], ah[cur][i], bh[j]);
        }

        if (s + NS - 1 < g.nslab) stage(s + NS - 1);
    }
}

// ---------------- fused Q+K projection (own launch; no waits) ----------------
// gridDim.z==2 selects WqT/WkT, bq/bk, Qs/Ks. C[s,n] = X * W^T + b, fp16.
__global__ void __launch_bounds__(NTHREADS, 2)
qkproj(const __half* __restrict__ Xh, const __half* __restrict__ Wh,
       const float* __restrict__ bq, const float* __restrict__ bk,
       __half* __restrict__ Qs, __half* __restrict__ Ks)
{
    extern __shared__ __align__(16) char smraw[];
    const uint32_t sb = smem_u32(smraw);

    const int tid = threadIdx.x;
    const int wid = tid >> 5;
    const int lane = tid & 31;
    const int z = blockIdx.z;
    const long m0 = (long)blockIdx.y * TM;
    const long n0 = (long)blockIdx.x * TN;

    const float* bp = z ? bk : bq;
    __half* C = z ? Ks : Qs;

    const int wm = (wid & 1) * 64;
    const int wn = (wid >> 1) * 64;

    float acc[4][8][4];
#pragma unroll
    for (int i = 0; i < 4; i++)
#pragma unroll
        for (int j = 0; j < 8; j++)
#pragma unroll
            for (int e = 0; e < 4; e++) acc[i][j][e] = 0.f;

    MainloopArgs g;
    g.sb = sb;
    g.pA = (const char*)(Xh + m0 * 1024);
    g.pB = (const char*)(Wh + (long)z * 1048576L + n0 * 1024);
    g.ldab = 2048; g.ldbb = 2048;
    g.aOffBase = (wm + (lane & 15)) * (RS * 2) + ((lane >> 4) << 4);
    g.bOffBase = (wn + ((lane >> 4) << 3) + (lane & 7)) * (RS * 2) + (((lane >> 3) & 1) << 4);
    g.nslab = 16;
    g.tid = tid;
    run_mainloop(g, acc);

#pragma unroll
    for (int i = 0; i < 4; i++) {
        const long r0 = m0 + wm + i * 16 + (lane >> 2);
        const long r1 = r0 + 8;
#pragma unroll
        for (int j = 0; j < 8; j++) {
            const int cb = (int)n0 + wn + j * 8 + (lane & 3) * 2;
            const float b0 = bp[cb], b1 = bp[cb + 1];
            *(uint32_t*)(C + r0 * 1024 + cb) =
                packh(__float2half_rn(acc[i][j][0] + b0),
                      __float2half_rn(acc[i][j][1] + b1));
            *(uint32_t*)(C + r1 * 1024 + cb) =
                packh(__float2half_rn(acc[i][j][2] + b0),
                      __float2half_rn(acc[i][j][3] + b1));
        }
    }
}

// ---------------- mega2: Vt + scores + PV, ticket-ordered ----------------
// tickets: [0,1024) Vt-proj   [1024,5120) scores   [5120,6144) PV
// Only PV waits (on cnt_sc / cnt_vt); Vt and scores run wait-free.
__global__ void __launch_bounds__(NTHREADS, 2)
mega2(const __half* __restrict__ Xh, const __half* __restrict__ Wh,
      const float* __restrict__ bv,
      const __half* __restrict__ Qs, const __half* __restrict__ Ks,
      __half* __restrict__ Vt, __half* __restrict__ Ph,
      float* __restrict__ rs, int* __restrict__ ctl,
      float* __restrict__ out)
{
    extern __shared__ __align__(16) char smraw[];
    const uint32_t sb = smem_u32(smraw);

    const int tid = threadIdx.x;
    const int wid = tid >> 5;
    const int lane = tid & 31;
    const int wm = (wid & 1) * 64;
    const int wn = (wid >> 1) * 64;
    const int aOffBase = (wm + (lane & 15)) * (RS * 2) + ((lane >> 4) << 4);
    const int bOffBase = (wn + ((lane >> 4) << 3) + (lane & 7)) * (RS * 2) + (((lane >> 3) & 1) << 4);

    __shared__ int s_t;
    if (tid == 0) s_t = atomicAdd(&ctl[0], 1);
    __syncthreads();
    const int t = s_t;

    float acc[4][8][4];
#pragma unroll
    for (int i = 0; i < 4; i++)
#pragma unroll
        for (int j = 0; j < 8; j++)
#pragma unroll
            for (int e = 0; e < 4; e++) acc[i][j][e] = 0.f;

    MainloopArgs g;
    g.sb = sb;
    g.aOffBase = aOffBase;
    g.bOffBase = bOffBase;
    g.tid = tid;

    if (t < 1024) {
        // ---- Vt projection: Vt[n, s] = WvT x X^T + bv(row), per batch ----
        const long bz = t >> 8;
        const int tt = t & 255;
        const int ntile = tt >> 5;
        const long m0 = (long)ntile * TM;
        const long n0 = (long)(tt & 31) * TN;

        g.pA = (const char*)(Wh + 2097152L + m0 * 1024);
        g.pB = (const char*)(Xh + bz * 4194304L + n0 * 1024);
        g.ldab = 2048; g.ldbb = 2048; g.nslab = 16;
        run_mainloop(g, acc);

        __half* outb = Vt + bz * 4194304L;
#pragma unroll
        for (int i = 0; i < 4; i++) {
            const long r0 = m0 + wm + i * 16 + (lane >> 2);
            const long r1 = r0 + 8;
            const float rb0 = bv[r0], rb1 = bv[r1];
#pragma unroll
            for (int j = 0; j < 8; j++) {
                const int cb = (int)n0 + wn + j * 8 + (lane & 3) * 2;
                *(uint32_t*)(outb + r0 * 4096 + cb) =
                    packh(__float2half_rn(acc[i][j][0] + rb0),
                          __float2half_rn(acc[i][j][1] + rb0));
                *(uint32_t*)(outb + r1 * 4096 + cb) =
                    packh(__float2half_rn(acc[i][j][2] + rb1),
                          __float2half_rn(acc[i][j][3] + rb1));
            }
        }
        arrive_cnt(&ctl[CTL_VT + (int)bz * 8 + ntile]);

    } else if (t < 5120) {
        // ---- scores: Ph = exp((1/32) Q K^T) + rowsum atomics ----
        const int t2 = t - 1024;
        const long bz = t2 >> 10;
        const int tt = t2 & 1023;
        const int yt = tt >> 5, xt = tt & 31;
        const long m0 = (long)yt * TM;
        const long n0 = (long)xt * TN;

        g.pA = (const char*)(Qs + bz * 4194304L + m0 * 1024);
        g.pB = (const char*)(Ks + bz * 4194304L + n0 * 1024);
        g.ldab = 2048; g.ldbb = 2048; g.nslab = 16;
        run_mainloop(g, acc);

        __half* outb = Ph + bz * 16777216L;
#pragma unroll
        for (int i = 0; i < 4; i++) {
            const long r0 = m0 + wm + i * 16 + (lane >> 2);
            const long r1 = r0 + 8;
            float s0 = 0.f, s1 = 0.f;
#pragma unroll
            for (int j = 0; j < 8; j++) {
                const int cb = (int)n0 + wn + j * 8 + (lane & 3) * 2;
                const float e0 = __expf(0.03125f * acc[i][j][0]);
                const float e1 = __expf(0.03125f * acc[i][j][1]);
                const float e2 = __expf(0.03125f * acc[i][j][2]);
                const float e3 = __expf(0.03125f * acc[i][j][3]);
                s0 += e0 + e1;
                s1 += e2 + e3;
                *(uint32_t*)(outb + r0 * 4096 + cb) =
                    packh(__float2half_rn(e0), __float2half_rn(e1));
                *(uint32_t*)(outb + r1 * 4096 + cb) =
                    packh(__float2half_rn(e2), __float2half_rn(e3));
            }
            s0 += __shfl_xor_sync(0xffffffffu, s0, 1);
            s0 += __shfl_xor_sync(0xffffffffu, s0, 2);
            s1 += __shfl_xor_sync(0xffffffffu, s1, 1);
            s1 += __shfl_xor_sync(0xffffffffu, s1, 2);
            if ((lane & 3) == 0) {
                atomicAdd(&rs[bz * 4096 + r0], s0);
                atomicAdd(&rs[bz * 4096 + r1], s1);
            }
        }
        arrive_cnt(&ctl[CTL_SC + (int)bz * 32 + yt]);

    } else {
        // ---- PV: out = (P~ V) / rowsum, fp32 ----
        const int t2 = t - 5120;
        const long bz = t2 >> 8;
        const int tt = t2 & 255;
        const int yt = tt >> 3;                   // m tile of 4096
        const int xt = tt & 7;                    // n tile of 1024
        const long m0 = (long)yt * TM;
        const long n0 = (long)xt * TN;

        wait_cnt(&ctl[CTL_SC + (int)bz * 32 + yt], 32);   // Ph row + rowsum final
        wait_cnt(&ctl[CTL_VT + (int)bz * 8 + xt], 32);    // Vt cols ready

        g.pA = (const char*)(Ph + bz * 16777216L + m0 * 4096);
        g.pB = (const char*)(Vt + bz * 4194304L + n0 * 4096);
        g.ldab = 8192; g.ldbb = 8192; g.nslab = 64;
        run_mainloop(g, acc);

        float* outb = out + bz * 4194304L;
#pragma unroll
        for (int i = 0; i < 4; i++) {
            const long r0 = m0 + wm + i * 16 + (lane >> 2);
            const long r1 = r0 + 8;
            const float inv0 = __frcp_rn(__ldg(&rs[bz * 4096 + r0]));
            const float inv1 = __frcp_rn(__ldg(&rs[bz * 4096 + r1]));
#pragma unroll
            for (int j = 0; j < 8; j++) {
                const int cb = (int)n0 + wn + j * 8 + (lane & 3) * 2;
                *(float2*)(outb + r0 * 1024 + cb) =
                    make_float2(acc[i][j][0] * inv0, acc[i][j][1] * inv0);
                *(float2*)(outb + r1 * 1024 + cb) =
                    make_float2(acc[i][j][2] * inv1, acc[i][j][3] * inv1);
            }
        }
    }
}

// ---------------- pre passes ----------------
__global__ void __launch_bounds__(256) convert_x(const float4* __restrict__ x,
                                                 uint2* __restrict__ h)
{
    long i = (long)blockIdx.x * 256 + threadIdx.x;
    float4 v = x[i];
    h[i] = make_uint2(packh(__float2half_rn(v.x), __float2half_rn(v.y)),
                      packh(__float2half_rn(v.z), __float2half_rn(v.w)));
}

// W[e,n] -> Wt[n,e] fp16
__global__ void __launch_bounds__(256) convert_wt(const float* __restrict__ W0,
                                                  const float* __restrict__ W1,
                                                  const float* __restrict__ W2,
                                                  __half* __restrict__ hi)
{
    const float* W = (blockIdx.z == 0) ? W0 : (blockIdx.z == 1) ? W1 : W2;
    __half* ho = hi + (long)blockIdx.z * 1048576;
    __shared__ float t[32][33];
    const int e0 = blockIdx.x * 32, n0 = blockIdx.y * 32;
    const int lx = threadIdx.x & 31, ly = threadIdx.x >> 5;
#pragma unroll
    for (int j = 0; j < 4; j++)
        t[ly + 8 * j][lx] = W[(long)(e0 + ly + 8 * j) * 1024 + n0 + lx];
    __syncthreads();
#pragma unroll
    for (int j = 0; j < 4; j++)
        ho[(long)(n0 + ly + 8 * j) * 1024 + e0 + lx] = __float2half_rn(t[lx][ly + 8 * j]);
}

// ---------------- launch ----------------
extern "C" void kernel_launch(void* const* d_in, const int* in_sizes, int n_in,
                              void* d_out, int out_size)
{
    const float* x  = (const float*)d_in[0];
    const float* Wq = (const float*)d_in[1];
    const float* bq = (const float*)d_in[2];
    const float* Wk = (const float*)d_in[3];
    const float* bk = (const float*)d_in[4];
    const float* Wv = (const float*)d_in[5];
    const float* bv = (const float*)d_in[6];
    float* out = (float*)d_out;

    __half *Xh, *Wh, *Qs, *Ks, *Vt, *Ph;
    float* rs;
    int* ctl;
    cudaGetSymbolAddress((void**)&Xh, g_Xh);
    cudaGetSymbolAddress((void**)&Wh, g_Wh);
    cudaGetSymbolAddress((void**)&Qs, g_Qs);
    cudaGetSymbolAddress((void**)&Ks, g_Ks);
    cudaGetSymbolAddress((void**)&Vt, g_Vt);
    cudaGetSymbolAddress((void**)&Ph, g_Ph);
    cudaGetSymbolAddress((void**)&rs, g_rs);
    cudaGetSymbolAddress((void**)&ctl, g_ctl);

    cudaFuncSetAttribute(qkproj, cudaFuncAttributeMaxDynamicSharedMemorySize, SMEM_DYN);
    cudaFuncSetAttribute(mega2, cudaFuncAttributeMaxDynamicSharedMemorySize, SMEM_DYN);

    // 0. reset ticket/counters + softmax denominators
    cudaMemsetAsync(ctl, 0, 512 * sizeof(int));
    cudaMemsetAsync(rs, 0, 16384 * sizeof(float));

    // 1. operand conversion
    convert_x<<<16384, 256>>>((const float4*)x, (uint2*)Xh);
    convert_wt<<<dim3(32, 32, 3), 256>>>(Wq, Wk, Wv, Wh);

    // 2. fused Q+K projections (wait-free, own launch)
    qkproj<<<dim3(8, 128, 2), NTHREADS, SMEM_DYN>>>(Xh, Wh, bq, bk, Qs, Ks);

    // 3. mega2: Vt + scores(+exp+rowsum) + PV in one ticket-ordered launch
    mega2<<<6144, NTHREADS, SMEM_DYN>>>(
        Xh, Wh, bv, Qs, Ks, Vt, Ph, rs, ctl, out);
}